// round 10
// baseline (speedup 1.0000x reference)
#include <cuda_runtime.h>
#include <cuda_bf16.h>
#include <math.h>
#include <stdint.h>

#define N_NODES 8192
#define HIDDEN  256
#define HEADS   4
#define HEAD_DIM 64
#define NUM_EDGES 4096
#define NUM_INC 65536
#define LN_EPS 1e-5f

// ---------------- scratch (device globals; no allocation allowed) -------------
__device__ float4   g_u4[HIDDEN];              // folded W_w x edge_att, [j].h
__device__ float    g_c[HEADS];                // folded W_b x edge_att
__device__ float4   g_logit[N_NODES];          // per-node logits, 4 heads
__device__ float    g_segsum[NUM_EDGES * HEADS];
__device__ float4   g_rseg[NUM_EDGES];         // valid ? 0.25/segsum : 0
__device__ int      g_ecount[NUM_EDGES];
__device__ int      g_eoffset[NUM_EDGES];
__device__ int      g_epos[NUM_EDGES];
__device__ float    g_snode[N_NODES];
__device__ int      g_cnode[N_NODES];
__device__ int      g_noffset[N_NODES];
__device__ int      g_npos[N_NODES];
__device__ int      g_sorted_node[NUM_INC];    // edge-CSR: member node ids
__device__ int      g_ne[NUM_INC];             // node-CSR: edge id per incidence
__device__ float    g_na[NUM_INC];             // node-CSR: attn_mean per incidence
__device__ float    g_y[N_NODES * HIDDEN];     // x @ out_w^T

__device__ __forceinline__ uint32_t smem_u32(const void* p) {
    uint32_t a;
    asm("{ .reg .u64 t; cvta.to.shared.u64 t, %1; cvt.u32.u64 %0, t; }"
        : "=r"(a) : "l"(p));
    return a;
}

// ---------------- K0: init scratch + fold weights (last block) ----------------
__global__ void k_init_prep(const float* __restrict__ W_w, const float* __restrict__ W_b,
                            const float* __restrict__ edge_att) {
    if (blockIdx.x == gridDim.x - 1) {
        __shared__ float ea[HEADS * HEAD_DIM];
        int j = threadIdx.x;
        ea[j] = edge_att[j];
        __syncthreads();
        float acc[HEADS];
        #pragma unroll
        for (int h = 0; h < HEADS; h++) {
            float s = 0.f;
            #pragma unroll 8
            for (int d = 0; d < HEAD_DIM; d++)
                s += W_w[(h * HEAD_DIM + d) * HIDDEN + j] * ea[h * HEAD_DIM + d];
            acc[h] = s;
        }
        g_u4[j] = make_float4(acc[0], acc[1], acc[2], acc[3]);
        if (j < HEADS) {
            float s = 0.f;
            for (int d = 0; d < HEAD_DIM; d++)
                s += W_b[j * HEAD_DIM + d] * ea[j * HEAD_DIM + d];
            g_c[j] = s;
        }
        return;
    }
    int i = blockIdx.x * blockDim.x + threadIdx.x;
    if (i < NUM_EDGES * HEADS) g_segsum[i] = 0.f;
    if (i < NUM_EDGES) { g_ecount[i] = 0; g_epos[i] = 0; }
    if (i < N_NODES) { g_snode[i] = 0.f; g_cnode[i] = 0; g_npos[i] = 0; }
}

// ---------------- K1: per-node logits (one warp per node, float4 loads) -------
__global__ void k_logit(const float* __restrict__ x) {
    int warp = (blockIdx.x * blockDim.x + threadIdx.x) >> 5;
    int lane = threadIdx.x & 31;
    if (warp >= N_NODES) return;
    const float4* xr4 = (const float4*)(x + (size_t)warp * HIDDEN);
    float4 a = __ldg(&xr4[lane * 2]);
    float4 b = __ldg(&xr4[lane * 2 + 1]);
    float xv[8] = {a.x, a.y, a.z, a.w, b.x, b.y, b.z, b.w};
    float s0 = 0.f, s1 = 0.f, s2 = 0.f, s3 = 0.f;
    #pragma unroll
    for (int t = 0; t < 8; t++) {
        float4 u = g_u4[lane * 8 + t];
        s0 += xv[t] * u.x; s1 += xv[t] * u.y; s2 += xv[t] * u.z; s3 += xv[t] * u.w;
    }
    #pragma unroll
    for (int off = 16; off; off >>= 1) {
        s0 += __shfl_xor_sync(0xffffffffu, s0, off);
        s1 += __shfl_xor_sync(0xffffffffu, s1, off);
        s2 += __shfl_xor_sync(0xffffffffu, s2, off);
        s3 += __shfl_xor_sync(0xffffffffu, s3, off);
    }
    if (lane == 0)
        g_logit[warp] = make_float4(s0 + g_c[0], s1 + g_c[1], s2 + g_c[2], s3 + g_c[3]);
}

// ---------------- K2: pass1 — one thread per (incidence, head) ----------------
// Softmax shift removed: logits are bounded, exp is safe, and p/segsum is
// analytically identical to the max-subtracted reference.
__global__ void k_pass1(const int* __restrict__ node_idx, const int* __restrict__ edge_idx) {
    int t = blockIdx.x * blockDim.x + threadIdx.x;
    if (t >= NUM_INC * HEADS) return;
    int i = t >> 2, h = t & 3;
    int n = node_idx[i], e = edge_idx[i];
    float l = ((const float*)g_logit)[n * HEADS + h];
    atomicAdd(&g_segsum[e * HEADS + h], expf(l));
    if (h == 0) {
        atomicAdd(&g_ecount[e], 1);
        atomicAdd(&g_cnode[n], 1);
    }
}

// ---------------- K3: scans — block 0: edges(+rseg), block 1: nodes -----------
__global__ void k_scan() {
    __shared__ int sh[1024];
    int t = threadIdx.x;
    if (blockIdx.x == 0) {
        int local[4];
        int s = 0;
        #pragma unroll
        for (int i = 0; i < 4; i++) { local[i] = g_ecount[t * 4 + i]; s += local[i]; }
        sh[t] = s;
        __syncthreads();
        for (int off = 1; off < 1024; off <<= 1) {
            int add = (t >= off) ? sh[t - off] : 0;
            __syncthreads();
            sh[t] += add;
            __syncthreads();
        }
        int excl = sh[t] - s;
        #pragma unroll
        for (int i = 0; i < 4; i++) {
            int e = t * 4 + i;
            g_eoffset[e] = excl; excl += local[i];
            float4 r;
            if (local[i] >= 2) {
                r.x = 0.25f / g_segsum[e * HEADS + 0];
                r.y = 0.25f / g_segsum[e * HEADS + 1];
                r.z = 0.25f / g_segsum[e * HEADS + 2];
                r.w = 0.25f / g_segsum[e * HEADS + 3];
            } else {
                r = make_float4(0.f, 0.f, 0.f, 0.f);
            }
            g_rseg[e] = r;
        }
    } else {
        int local[8];
        int s = 0;
        #pragma unroll
        for (int i = 0; i < 8; i++) { local[i] = g_cnode[t * 8 + i]; s += local[i]; }
        sh[t] = s;
        __syncthreads();
        for (int off = 1; off < 1024; off <<= 1) {
            int add = (t >= off) ? sh[t - off] : 0;
            __syncthreads();
            sh[t] += add;
            __syncthreads();
        }
        int excl = sh[t] - s;
        #pragma unroll
        for (int i = 0; i < 8; i++) { g_noffset[t * 8 + i] = excl; excl += local[i]; }
    }
}

// ---------------- K4: pass2 — attn_mean, node sums, both CSR scatters ---------
__global__ void k_pass2(const int* __restrict__ node_idx, const int* __restrict__ edge_idx) {
    int i = blockIdx.x * blockDim.x + threadIdx.x;
    if (i >= NUM_INC) return;
    int n = node_idx[i], e = edge_idx[i];
    float4 l = g_logit[n];
    float4 r = g_rseg[e];
    float am = expf(l.x) * r.x + expf(l.y) * r.y + expf(l.z) * r.z + expf(l.w) * r.w;
    atomicAdd(&g_snode[n], am);
    // edge-CSR (members of each edge)
    int pos = atomicAdd(&g_epos[e], 1);
    g_sorted_node[g_eoffset[e] + pos] = n;
    // node-CSR (edges of each node, with attn)
    int pos2 = atomicAdd(&g_npos[n], 1);
    int nidx = g_noffset[n] + pos2;
    g_ne[nidx] = e;
    g_na[nidx] = am;
}

// ---------------- K5: fp32 GEMM  y = x @ out_w^T ------------------------------
__global__ void k_gemm(const float* __restrict__ X, const float* __restrict__ W) {
    __shared__ float As[16][64];
    __shared__ float Ws[16][64];
    int m0 = blockIdx.y * 64;
    int n0 = blockIdx.x * 64;
    int tid = threadIdx.x;
    int tx = tid & 15;
    int ty = tid >> 4;
    int lr = tid >> 2;
    int lk = (tid & 3) * 4;

    float acc[4][4];
    #pragma unroll
    for (int i = 0; i < 4; i++)
        #pragma unroll
        for (int j = 0; j < 4; j++) acc[i][j] = 0.f;

    for (int kt = 0; kt < HIDDEN; kt += 16) {
        float4 av = *(const float4*)&X[(size_t)(m0 + lr) * HIDDEN + kt + lk];
        float4 wv = *(const float4*)&W[(size_t)(n0 + lr) * HIDDEN + kt + lk];
        As[lk + 0][lr] = av.x; As[lk + 1][lr] = av.y; As[lk + 2][lr] = av.z; As[lk + 3][lr] = av.w;
        Ws[lk + 0][lr] = wv.x; Ws[lk + 1][lr] = wv.y; Ws[lk + 2][lr] = wv.z; Ws[lk + 3][lr] = wv.w;
        __syncthreads();
        #pragma unroll
        for (int kk = 0; kk < 16; kk++) {
            float a[4], b[4];
            #pragma unroll
            for (int i = 0; i < 4; i++) a[i] = As[kk][ty * 4 + i];
            #pragma unroll
            for (int j = 0; j < 4; j++) b[j] = Ws[kk][tx * 4 + j];
            #pragma unroll
            for (int i = 0; i < 4; i++)
                #pragma unroll
                for (int j = 0; j < 4; j++) acc[i][j] += a[i] * b[j];
        }
        __syncthreads();
    }
    #pragma unroll
    for (int i = 0; i < 4; i++) {
        float4 v = make_float4(acc[i][0], acc[i][1], acc[i][2], acc[i][3]);
        *(float4*)&g_y[(size_t)(m0 + ty * 4 + i) * HIDDEN + n0 + tx * 4] = v;
    }
}

// ---------------- K6: scale + bias + LayerNorm --------------------------------
__global__ void k_ln(const float* __restrict__ out_b, float* __restrict__ out) {
    int n = blockIdx.x;
    int t = threadIdx.x;
    int lane = t & 31, wid = t >> 5;
    __shared__ float sh[8];
    float alpha = g_snode[n] / fmaxf((float)g_cnode[n], 1.0f);
    float v = alpha * g_y[(size_t)n * HIDDEN + t] + out_b[t];

    float s = v;
    #pragma unroll
    for (int off = 16; off; off >>= 1) s += __shfl_xor_sync(0xffffffffu, s, off);
    if (lane == 0) sh[wid] = s;
    __syncthreads();
    float tot = 0.f;
    #pragma unroll
    for (int w = 0; w < 8; w++) tot += sh[w];
    float mu = tot * (1.0f / HIDDEN);
    __syncthreads();

    float d = v - mu;
    float s2 = d * d;
    #pragma unroll
    for (int off = 16; off; off >>= 1) s2 += __shfl_xor_sync(0xffffffffu, s2, off);
    if (lane == 0) sh[wid] = s2;
    __syncthreads();
    float tot2 = 0.f;
    #pragma unroll
    for (int w = 0; w < 8; w++) tot2 += sh[w];
    float var = tot2 * (1.0f / HIDDEN);

    out[(size_t)n * HIDDEN + t] = d * rsqrtf(var + LN_EPS);
}

// ---------------- K7: AW row construction — one block per node row ------------
// Builds AW[i,:] in a 32KB SMEM row, then issues ONE TMA bulk store of the
// whole row (cp.async.bulk SMEM->GMEM). No zero prepass, no global atomics,
// no per-thread store issue: DRAM traffic = exactly one 256MB TMA write.
__global__ __launch_bounds__(256) void k_aw_row(float* __restrict__ AW) {
    __shared__ __align__(16) float row[N_NODES];   // 32 KB
    int i = blockIdx.x;
    float4* r4 = (float4*)row;
    float4 z = make_float4(0.f, 0.f, 0.f, 0.f);
    #pragma unroll
    for (int t = threadIdx.x; t < N_NODES / 4; t += 256) r4[t] = z;
    __syncthreads();

    int beg = g_noffset[i];
    int cnt = g_cnode[i];
    int warp = threadIdx.x >> 5, lane = threadIdx.x & 31;
    for (int k = warp; k < cnt; k += 8) {          // one warp per incident edge
        int e = g_ne[beg + k];
        float am = g_na[beg + k];
        if (am != 0.f) {
            int mb = g_eoffset[e], m = g_ecount[e];
            for (int t = lane; t < m; t += 32)
                atomicAdd(&row[g_sorted_node[mb + t]], am);
        }
    }
    __syncthreads();
    if (threadIdx.x == 0) {
        row[i] = 0.f;                              // zero diagonal
        asm volatile("fence.proxy.async.shared::cta;" ::: "memory");
        uint64_t gptr = (uint64_t)(AW + (size_t)i * N_NODES);
        uint32_t saddr = smem_u32(row);
        asm volatile(
            "cp.async.bulk.global.shared::cta.bulk_group [%0], [%1], %2;"
            :: "l"(gptr), "r"(saddr), "n"(N_NODES * 4) : "memory");
        asm volatile("cp.async.bulk.commit_group;" ::: "memory");
        asm volatile("cp.async.bulk.wait_group 0;" ::: "memory");
    }
}

// ---------------- launch ------------------------------------------------------
static cudaStream_t s_gemm = nullptr;
static cudaEvent_t ev_fork = nullptr, ev_pass2 = nullptr, ev_ln = nullptr;

extern "C" void kernel_launch(void* const* d_in, const int* in_sizes, int n_in,
                              void* d_out, int out_size) {
    const float* x        = (const float*)d_in[0];
    const int*   node_idx = (const int*)d_in[1];
    const int*   edge_idx = (const int*)d_in[2];
    const float* W_w      = (const float*)d_in[3];
    const float* W_b      = (const float*)d_in[4];
    const float* edge_att = (const float*)d_in[5];
    const float* out_w    = (const float*)d_in[6];
    const float* out_b    = (const float*)d_in[7];

    float* out = (float*)d_out;                         // [8192, 256]
    float* AW  = out + (size_t)N_NODES * HIDDEN;        // [8192, 8192]

    if (s_gemm == nullptr) {
        cudaStreamCreateWithFlags(&s_gemm, cudaStreamNonBlocking);
        cudaEventCreateWithFlags(&ev_fork, cudaEventDisableTiming);
        cudaEventCreateWithFlags(&ev_pass2, cudaEventDisableTiming);
        cudaEventCreateWithFlags(&ev_ln, cudaEventDisableTiming);
    }

    // fork GEMM stream off the capture-origin stream
    cudaEventRecord(ev_fork, 0);
    cudaStreamWaitEvent(s_gemm, ev_fork, 0);

    // side stream: independent dense GEMM (overlaps the incidence chain)
    k_gemm<<<dim3(HIDDEN / 64, N_NODES / 64), 256, 0, s_gemm>>>(x, out_w);

    // main chain: incidence processing
    k_init_prep<<<64 + 1, 256>>>(W_w, W_b, edge_att);
    k_logit<<<N_NODES * 32 / 256, 256>>>(x);
    k_pass1<<<NUM_INC * HEADS / 256, 256>>>(node_idx, edge_idx);
    k_scan<<<2, 1024>>>();
    k_pass2<<<NUM_INC / 256, 256>>>(node_idx, edge_idx);
    cudaEventRecord(ev_pass2, 0);

    // long pole first: AW rows start right after pass2 on the main stream
    k_aw_row<<<N_NODES, 256>>>(AW);

    // LN on the gemm stream (needs gemm + pass2), overlaps aw_row
    cudaStreamWaitEvent(s_gemm, ev_pass2, 0);
    k_ln<<<N_NODES, HIDDEN, 0, s_gemm>>>(out_b, out);
    cudaEventRecord(ev_ln, s_gemm);

    // join
    cudaStreamWaitEvent(0, ev_ln, 0);
}

// round 14
// speedup vs baseline: 1.0161x; 1.0161x over previous
#include <cuda_runtime.h>
#include <cuda_bf16.h>
#include <math.h>
#include <stdint.h>

#define N_NODES 8192
#define HIDDEN  256
#define HEADS   4
#define HEAD_DIM 64
#define NUM_EDGES 4096
#define NUM_INC 65536
#define LN_EPS 1e-5f
#define AW_BLOCKS 444   // 148 SMs x 3 resident blocks

// ---------------- scratch (device globals; no allocation allowed) -------------
__device__ float4   g_u4[HIDDEN];              // folded W_w x edge_att, [j].h
__device__ float    g_c[HEADS];                // folded W_b x edge_att
__device__ float4   g_logit[N_NODES];          // per-node logits, 4 heads
__device__ float    g_segsum[NUM_EDGES * HEADS];
__device__ float4   g_rseg[NUM_EDGES];         // valid ? 0.25/segsum : 0
__device__ int      g_ecount[NUM_EDGES];
__device__ int      g_eoffset[NUM_EDGES];
__device__ int      g_epos[NUM_EDGES];
__device__ float    g_snode[N_NODES];
__device__ int      g_cnode[N_NODES];
__device__ int      g_noffset[N_NODES];
__device__ int      g_npos[N_NODES];
__device__ int      g_sorted_node[NUM_INC];    // edge-CSR: member node ids
__device__ int      g_ne[NUM_INC];             // node-CSR: edge id per incidence
__device__ float    g_na[NUM_INC];             // node-CSR: attn_mean per incidence
__device__ float    g_y[N_NODES * HIDDEN];     // x @ out_w^T

__device__ __forceinline__ uint32_t smem_u32(const void* p) {
    uint32_t a;
    asm("{ .reg .u64 t; cvta.to.shared.u64 t, %1; cvt.u32.u64 %0, t; }"
        : "=r"(a) : "l"(p));
    return a;
}
__device__ __forceinline__ uint32_t f2tf32(float v) {
    uint32_t h;
    asm("cvt.rna.tf32.f32 %0, %1;" : "=r"(h) : "f"(v));
    return h;
}

// ---------------- K0: init scratch + fold weights (last block) ----------------
__global__ void k_init_prep(const float* __restrict__ W_w, const float* __restrict__ W_b,
                            const float* __restrict__ edge_att) {
    if (blockIdx.x == gridDim.x - 1) {
        __shared__ float ea[HEADS * HEAD_DIM];
        int j = threadIdx.x;
        ea[j] = edge_att[j];
        __syncthreads();
        float acc[HEADS];
        #pragma unroll
        for (int h = 0; h < HEADS; h++) {
            float s = 0.f;
            #pragma unroll 8
            for (int d = 0; d < HEAD_DIM; d++)
                s += W_w[(h * HEAD_DIM + d) * HIDDEN + j] * ea[h * HEAD_DIM + d];
            acc[h] = s;
        }
        g_u4[j] = make_float4(acc[0], acc[1], acc[2], acc[3]);
        if (j < HEADS) {
            float s = 0.f;
            for (int d = 0; d < HEAD_DIM; d++)
                s += W_b[j * HEAD_DIM + d] * ea[j * HEAD_DIM + d];
            g_c[j] = s;
        }
        return;
    }
    int i = blockIdx.x * blockDim.x + threadIdx.x;
    if (i < NUM_EDGES * HEADS) g_segsum[i] = 0.f;
    if (i < NUM_EDGES) { g_ecount[i] = 0; g_epos[i] = 0; }
    if (i < N_NODES) { g_snode[i] = 0.f; g_cnode[i] = 0; g_npos[i] = 0; }
}

// ---------------- K1: per-node logits (one warp per node, float4 loads) -------
__global__ void k_logit(const float* __restrict__ x) {
    int warp = (blockIdx.x * blockDim.x + threadIdx.x) >> 5;
    int lane = threadIdx.x & 31;
    if (warp >= N_NODES) return;
    const float4* xr4 = (const float4*)(x + (size_t)warp * HIDDEN);
    float4 a = __ldg(&xr4[lane * 2]);
    float4 b = __ldg(&xr4[lane * 2 + 1]);
    float xv[8] = {a.x, a.y, a.z, a.w, b.x, b.y, b.z, b.w};
    float s0 = 0.f, s1 = 0.f, s2 = 0.f, s3 = 0.f;
    #pragma unroll
    for (int t = 0; t < 8; t++) {
        float4 u = g_u4[lane * 8 + t];
        s0 += xv[t] * u.x; s1 += xv[t] * u.y; s2 += xv[t] * u.z; s3 += xv[t] * u.w;
    }
    #pragma unroll
    for (int off = 16; off; off >>= 1) {
        s0 += __shfl_xor_sync(0xffffffffu, s0, off);
        s1 += __shfl_xor_sync(0xffffffffu, s1, off);
        s2 += __shfl_xor_sync(0xffffffffu, s2, off);
        s3 += __shfl_xor_sync(0xffffffffu, s3, off);
    }
    if (lane == 0)
        g_logit[warp] = make_float4(s0 + g_c[0], s1 + g_c[1], s2 + g_c[2], s3 + g_c[3]);
}

// ---------------- K2: pass1 — one thread per (incidence, head) ----------------
// Softmax shift removed: logits are bounded, exp is safe, and p/segsum is
// analytically identical to the max-subtracted reference.
__global__ void k_pass1(const int* __restrict__ node_idx, const int* __restrict__ edge_idx) {
    int t = blockIdx.x * blockDim.x + threadIdx.x;
    if (t >= NUM_INC * HEADS) return;
    int i = t >> 2, h = t & 3;
    int n = node_idx[i], e = edge_idx[i];
    float l = ((const float*)g_logit)[n * HEADS + h];
    atomicAdd(&g_segsum[e * HEADS + h], expf(l));
    if (h == 0) {
        atomicAdd(&g_ecount[e], 1);
        atomicAdd(&g_cnode[n], 1);
    }
}

// ---------------- K3: scans — block 0: edges(+rseg), block 1: nodes -----------
__global__ void k_scan() {
    __shared__ int sh[1024];
    int t = threadIdx.x;
    if (blockIdx.x == 0) {
        int local[4];
        int s = 0;
        #pragma unroll
        for (int i = 0; i < 4; i++) { local[i] = g_ecount[t * 4 + i]; s += local[i]; }
        sh[t] = s;
        __syncthreads();
        for (int off = 1; off < 1024; off <<= 1) {
            int add = (t >= off) ? sh[t - off] : 0;
            __syncthreads();
            sh[t] += add;
            __syncthreads();
        }
        int excl = sh[t] - s;
        #pragma unroll
        for (int i = 0; i < 4; i++) {
            int e = t * 4 + i;
            g_eoffset[e] = excl; excl += local[i];
            float4 r;
            if (local[i] >= 2) {
                r.x = 0.25f / g_segsum[e * HEADS + 0];
                r.y = 0.25f / g_segsum[e * HEADS + 1];
                r.z = 0.25f / g_segsum[e * HEADS + 2];
                r.w = 0.25f / g_segsum[e * HEADS + 3];
            } else {
                r = make_float4(0.f, 0.f, 0.f, 0.f);
            }
            g_rseg[e] = r;
        }
    } else {
        int local[8];
        int s = 0;
        #pragma unroll
        for (int i = 0; i < 8; i++) { local[i] = g_cnode[t * 8 + i]; s += local[i]; }
        sh[t] = s;
        __syncthreads();
        for (int off = 1; off < 1024; off <<= 1) {
            int add = (t >= off) ? sh[t - off] : 0;
            __syncthreads();
            sh[t] += add;
            __syncthreads();
        }
        int excl = sh[t] - s;
        #pragma unroll
        for (int i = 0; i < 8; i++) { g_noffset[t * 8 + i] = excl; excl += local[i]; }
    }
}

// ---------------- K4: pass2 — attn_mean, node sums, both CSR scatters ---------
__global__ void k_pass2(const int* __restrict__ node_idx, const int* __restrict__ edge_idx) {
    int i = blockIdx.x * blockDim.x + threadIdx.x;
    if (i >= NUM_INC) return;
    int n = node_idx[i], e = edge_idx[i];
    float4 l = g_logit[n];
    float4 r = g_rseg[e];
    float am = expf(l.x) * r.x + expf(l.y) * r.y + expf(l.z) * r.z + expf(l.w) * r.w;
    atomicAdd(&g_snode[n], am);
    int pos = atomicAdd(&g_epos[e], 1);
    g_sorted_node[g_eoffset[e] + pos] = n;
    int pos2 = atomicAdd(&g_npos[n], 1);
    int nidx = g_noffset[n] + pos2;
    g_ne[nidx] = e;
    g_na[nidx] = am;
}

// ---------------- K5: tf32 tensor-core GEMM  y = x @ out_w^T ------------------
// M=8192, N=256, K=256. Block tile 64x64, 4 warps (2x2), warp tile 32x32.
// 2-term tf32 compensation: d += Ahi*Bhi + Ahi*Blo + Alo*Bhi  (~fp32 accuracy).
__global__ __launch_bounds__(128) void k_gemm(const float* __restrict__ X,
                                              const float* __restrict__ W) {
    __shared__ float Xs[64][36];
    __shared__ float Ws[64][36];
    int m0 = blockIdx.y * 64, n0 = blockIdx.x * 64;
    int tid = threadIdx.x;
    int warp = tid >> 5, lane = tid & 31;
    int wm = (warp >> 1) * 32, wn = (warp & 1) * 32;
    int g = lane >> 2, tg = lane & 3;

    float d[2][4][4];
    #pragma unroll
    for (int i = 0; i < 2; i++)
        #pragma unroll
        for (int j = 0; j < 4; j++)
            #pragma unroll
            for (int q = 0; q < 4; q++) d[i][j][q] = 0.f;

    for (int kt = 0; kt < HIDDEN; kt += 32) {
        #pragma unroll
        for (int l = 0; l < 4; l++) {
            int idx = tid + l * 128;
            int r = idx >> 3, c = (idx & 7) * 4;
            *(float4*)&Xs[r][c] = *(const float4*)&X[(size_t)(m0 + r) * HIDDEN + kt + c];
            *(float4*)&Ws[r][c] = *(const float4*)&W[(size_t)(n0 + r) * HIDDEN + kt + c];
        }
        __syncthreads();
        #pragma unroll
        for (int ks = 0; ks < 32; ks += 8) {
            uint32_t ah[2][4], al[2][4], bh[4][2], bl[4][2];
            #pragma unroll
            for (int i = 0; i < 2; i++)
                #pragma unroll
                for (int q = 0; q < 4; q++) {
                    // a0:(g,tg) a1:(g+8,tg) a2:(g,tg+4) a3:(g+8,tg+4)
                    float v = Xs[wm + i * 16 + g + (q & 1) * 8][ks + tg + (q >> 1) * 4];
                    uint32_t h = f2tf32(v);
                    ah[i][q] = h;
                    al[i][q] = f2tf32(v - __uint_as_float(h));
                }
            #pragma unroll
            for (int j = 0; j < 4; j++)
                #pragma unroll
                for (int q = 0; q < 2; q++) {
                    // b0:(k=tg, n=g) b1:(k=tg+4, n=g); B[k][n] = W[n][k]
                    float v = Ws[wn + j * 8 + g][ks + tg + q * 4];
                    uint32_t h = f2tf32(v);
                    bh[j][q] = h;
                    bl[j][q] = f2tf32(v - __uint_as_float(h));
                }
            #pragma unroll
            for (int i = 0; i < 2; i++)
                #pragma unroll
                for (int j = 0; j < 4; j++) {
                    float* dd = d[i][j];
                    #define MMA(AA, BB)                                              \
                        asm volatile(                                                \
                            "mma.sync.aligned.m16n8k8.row.col.f32.tf32.tf32.f32 "   \
                            "{%0,%1,%2,%3},{%4,%5,%6,%7},{%8,%9},{%0,%1,%2,%3};"    \
                            : "+f"(dd[0]), "+f"(dd[1]), "+f"(dd[2]), "+f"(dd[3])    \
                            : "r"(AA[0]), "r"(AA[1]), "r"(AA[2]), "r"(AA[3]),       \
                              "r"(BB[0]), "r"(BB[1]))
                    MMA(ah[i], bh[j]);
                    MMA(ah[i], bl[j]);
                    MMA(al[i], bh[j]);
                    #undef MMA
                }
        }
        __syncthreads();
    }
    #pragma unroll
    for (int i = 0; i < 2; i++)
        #pragma unroll
        for (int j = 0; j < 4; j++) {
            int row = m0 + wm + i * 16 + g;
            int col = n0 + wn + j * 8 + 2 * tg;
            g_y[(size_t)row * HIDDEN + col]           = d[i][j][0];
            g_y[(size_t)row * HIDDEN + col + 1]       = d[i][j][1];
            g_y[(size_t)(row + 8) * HIDDEN + col]     = d[i][j][2];
            g_y[(size_t)(row + 8) * HIDDEN + col + 1] = d[i][j][3];
        }
}

// ---------------- K6: scale + bias + LayerNorm --------------------------------
__global__ void k_ln(const float* __restrict__ out_b, float* __restrict__ out) {
    int n = blockIdx.x;
    int t = threadIdx.x;
    int lane = t & 31, wid = t >> 5;
    __shared__ float sh[8];
    float alpha = g_snode[n] / fmaxf((float)g_cnode[n], 1.0f);
    float v = alpha * g_y[(size_t)n * HIDDEN + t] + out_b[t];

    float s = v;
    #pragma unroll
    for (int off = 16; off; off >>= 1) s += __shfl_xor_sync(0xffffffffu, s, off);
    if (lane == 0) sh[wid] = s;
    __syncthreads();
    float tot = 0.f;
    #pragma unroll
    for (int w = 0; w < 8; w++) tot += sh[w];
    float mu = tot * (1.0f / HIDDEN);
    __syncthreads();

    float dv = v - mu;
    float s2 = dv * dv;
    #pragma unroll
    for (int off = 16; off; off >>= 1) s2 += __shfl_xor_sync(0xffffffffu, s2, off);
    if (lane == 0) sh[wid] = s2;
    __syncthreads();
    float tot2 = 0.f;
    #pragma unroll
    for (int w = 0; w < 8; w++) tot2 += sh[w];
    float var = tot2 * (1.0f / HIDDEN);

    out[(size_t)n * HIDDEN + t] = dv * rsqrtf(var + LN_EPS);
}

// ---------------- K7: AW rows — persistent, double-buffered TMA pipeline ------
// 444 persistent blocks (3/SM), each loops over rows. Row i is built in
// smem buf[p] while the TMA bulk store of the previous row drains; wait_group 1
// provides back-pressure before a buffer is reused. DRAM traffic = one 256MB
// streaming TMA write with no wave/tail overhead.
__global__ __launch_bounds__(256) void k_aw_row(float* __restrict__ AW) {
    extern __shared__ __align__(128) float buf[];   // 2 x N_NODES floats (64KB)
    float* b0 = buf;
    float* b1 = buf + N_NODES;
    int p = 0, issued = 0;
    for (int i = blockIdx.x; i < N_NODES; i += gridDim.x) {
        float* row = p ? b1 : b0;
        if (threadIdx.x == 0 && issued >= 2)
            asm volatile("cp.async.bulk.wait_group 1;" ::: "memory");
        __syncthreads();

        float4* r4 = (float4*)row;
        float4 z = make_float4(0.f, 0.f, 0.f, 0.f);
        #pragma unroll
        for (int t = threadIdx.x; t < N_NODES / 4; t += 256) r4[t] = z;
        __syncthreads();

        int beg = g_noffset[i];
        int cnt = g_cnode[i];
        int warp = threadIdx.x >> 5, lane = threadIdx.x & 31;
        for (int k = warp; k < cnt; k += 8) {
            int e = g_ne[beg + k];
            float am = g_na[beg + k];
            if (am != 0.f) {
                int mb = g_eoffset[e], m = g_ecount[e];
                for (int t = lane; t < m; t += 32)
                    atomicAdd(&row[g_sorted_node[mb + t]], am);
            }
        }
        __syncthreads();
        if (threadIdx.x == 0) {
            row[i] = 0.f;                           // zero diagonal
            asm volatile("fence.proxy.async.shared::cta;" ::: "memory");
            asm volatile(
                "cp.async.bulk.global.shared::cta.bulk_group [%0], [%1], %2;"
                :: "l"(AW + (size_t)i * N_NODES), "r"(smem_u32(row)),
                   "n"(N_NODES * 4) : "memory");
            asm volatile("cp.async.bulk.commit_group;" ::: "memory");
        }
        p ^= 1;
        issued++;
    }
    if (threadIdx.x == 0)
        asm volatile("cp.async.bulk.wait_group 0;" ::: "memory");
}

// ---------------- launch ------------------------------------------------------
static cudaStream_t s_gemm = nullptr;
static cudaEvent_t ev_fork = nullptr, ev_pass2 = nullptr, ev_ln = nullptr;

extern "C" void kernel_launch(void* const* d_in, const int* in_sizes, int n_in,
                              void* d_out, int out_size) {
    const float* x        = (const float*)d_in[0];
    const int*   node_idx = (const int*)d_in[1];
    const int*   edge_idx = (const int*)d_in[2];
    const float* W_w      = (const float*)d_in[3];
    const float* W_b      = (const float*)d_in[4];
    const float* edge_att = (const float*)d_in[5];
    const float* out_w    = (const float*)d_in[6];
    const float* out_b    = (const float*)d_in[7];

    float* out = (float*)d_out;                         // [8192, 256]
    float* AW  = out + (size_t)N_NODES * HIDDEN;        // [8192, 8192]

    if (s_gemm == nullptr) {
        cudaStreamCreateWithFlags(&s_gemm, cudaStreamNonBlocking);
        cudaEventCreateWithFlags(&ev_fork, cudaEventDisableTiming);
        cudaEventCreateWithFlags(&ev_pass2, cudaEventDisableTiming);
        cudaEventCreateWithFlags(&ev_ln, cudaEventDisableTiming);
        cudaFuncSetAttribute(k_aw_row, cudaFuncAttributeMaxDynamicSharedMemorySize,
                             2 * N_NODES * (int)sizeof(float));
    }

    // fork GEMM stream off the capture-origin stream
    cudaEventRecord(ev_fork, 0);
    cudaStreamWaitEvent(s_gemm, ev_fork, 0);

    // side stream: tensor-core GEMM
    k_gemm<<<dim3(HIDDEN / 64, N_NODES / 64), 128, 0, s_gemm>>>(x, out_w);

    // main chain: incidence processing
    k_init_prep<<<64 + 1, 256>>>(W_w, W_b, edge_att);
    k_logit<<<N_NODES * 32 / 256, 256>>>(x);
    k_pass1<<<NUM_INC * HEADS / 256, 256>>>(node_idx, edge_idx);
    k_scan<<<2, 1024>>>();
    k_pass2<<<NUM_INC / 256, 256>>>(node_idx, edge_idx);
    cudaEventRecord(ev_pass2, 0);

    // long pole: persistent pipelined AW rows
    k_aw_row<<<AW_BLOCKS, 256, 2 * N_NODES * sizeof(float)>>>(AW);

    // LN on the gemm stream (needs gemm + pass2), may overlap aw_row
    cudaStreamWaitEvent(s_gemm, ev_pass2, 0);
    k_ln<<<N_NODES, HIDDEN, 0, s_gemm>>>(out_b, out);
    cudaEventRecord(ev_ln, s_gemm);

    // join
    cudaStreamWaitEvent(0, ev_ln, 0);
}